// round 1
// baseline (speedup 1.0000x reference)
#include <cuda_runtime.h>

#define NROWS 65536
#define DDATA 512
#define DLAT  64
#define KC    64
#define TILE  256
#define NT    256
#define NITER 10
#define EPSV  1e-8f
#define ALPHA 0.001f

#define XPAD  68
#define RPAD  68
#define CTPAD 66

typedef unsigned long long ull;

__device__ float  g_C[KC * DLAT];
__device__ float  g_Cacc[KC * DLAT];
__device__ float  g_colsum[KC];
__device__ float  g_loss;
__device__ float  g_loss_final;
__device__ double g_dloss;

__device__ __forceinline__ ull pack2(float a, float b) {
    ull r; asm("mov.b64 %0, {%1, %2};" : "=l"(r) : "f"(a), "f"(b)); return r;
}
__device__ __forceinline__ void unpack2(ull v, float& a, float& b) {
    asm("mov.b64 {%0, %1}, %2;" : "=f"(a), "=f"(b) : "l"(v));
}
__device__ __forceinline__ ull ffma2(ull a, ull b, ull c) {
    ull d; asm("fma.rn.f32x2 %0, %1, %2, %3;" : "=l"(d) : "l"(a), "l"(b), "l"(c)); return d;
}

// ---------------------------------------------------------------------------
// init: C = enc[:64], zero accumulators
// ---------------------------------------------------------------------------
__global__ void init_kernel(const float* __restrict__ enc) {
    int i = blockIdx.x * blockDim.x + threadIdx.x;
    if (i < KC * DLAT) { g_C[i] = enc[i]; g_Cacc[i] = 0.f; }
    if (i < KC) g_colsum[i] = 0.f;
    if (i == 0) { g_loss = 0.f; g_loss_final = 0.f; g_dloss = 0.0; }
}

// ---------------------------------------------------------------------------
// decoder loss: sum (X - dec)^2 over 33.5M floats
// ---------------------------------------------------------------------------
__global__ void decoder_kernel(const float4* __restrict__ X,
                               const float4* __restrict__ D, int n4) {
    float s = 0.f;
    int stride = gridDim.x * blockDim.x;
    for (int i = blockIdx.x * blockDim.x + threadIdx.x; i < n4; i += stride) {
        float4 a = X[i], b = D[i];
        float dx = a.x - b.x, dy = a.y - b.y, dz = a.z - b.z, dw = a.w - b.w;
        s = fmaf(dx, dx, fmaf(dy, dy, fmaf(dz, dz, fmaf(dw, dw, s))));
    }
    __shared__ double rs[8];
    #pragma unroll
    for (int o = 16; o; o >>= 1) s += __shfl_xor_sync(0xffffffffu, s, o);
    if ((threadIdx.x & 31) == 0) rs[threadIdx.x >> 5] = (double)s;
    __syncthreads();
    if (threadIdx.x == 0) {
        double d = 0.0;
        #pragma unroll
        for (int w = 0; w < 8; w++) d += rs[w];
        atomicAdd(&g_dloss, d);
    }
}

// ---------------------------------------------------------------------------
// fused k-means iteration:
//   phase 1: d2[row][k] = max(|x|^2 + |c|^2 - 2 x.c, 0)    (f32x2 GEMM)
//   softmax: r = softmax(-d2) per row, loss += sum r*d2
//   phase 2: Cacc[k][j] += r[row][k]*x[row][j], colsum[k] += r   (f32x2 GEMM)
// ---------------------------------------------------------------------------
__global__ __launch_bounds__(NT, 1) void kmeans_iter(const float* __restrict__ enc) {
    extern __shared__ float sm[];
    float* x_s  = sm;                       // [TILE][XPAD]
    float* r_s  = x_s + TILE * XPAD;        // [TILE][RPAD]  d2 then r
    float* CT_s = r_s + TILE * RPAD;        // [DLAT][CTPAD] CT_s[j][k] = C[k][j]
    float* x2_s = CT_s + DLAT * CTPAD;      // [TILE]
    float* c2_s = x2_s + TILE;              // [KC]
    float* red  = c2_s + KC;                // [8]

    const int t = threadIdx.x;
    const int row0 = blockIdx.x * TILE;

    // load C transposed + x tile (coalesced)
    for (int i = t; i < KC * DLAT; i += NT) {
        int k = i >> 6, j = i & 63;
        CT_s[j * CTPAD + k] = g_C[i];
    }
    for (int i = t; i < TILE * DLAT; i += NT) {
        int r = i >> 6, j = i & 63;
        x_s[r * XPAD + j] = enc[(row0 + r) * DLAT + j];
    }
    __syncthreads();

    // per-row |x|^2 and per-cluster |c|^2
    {
        float s = 0.f;
        const float4* xr = (const float4*)&x_s[t * XPAD];
        #pragma unroll
        for (int q = 0; q < 16; ++q) {
            float4 v = xr[q];
            s = fmaf(v.x, v.x, fmaf(v.y, v.y, fmaf(v.z, v.z, fmaf(v.w, v.w, s))));
        }
        x2_s[t] = s;
    }
    if (t < KC) {
        float s = 0.f;
        #pragma unroll
        for (int j = 0; j < DLAT; ++j) {
            float v = CT_s[j * CTPAD + t];
            s = fmaf(v, v, s);
        }
        c2_s[t] = s;
    }
    __syncthreads();

    // ---- phase 1: 8-row x 8-k micro-tile per thread, f32x2 packed over k-pairs
    {
        const int tx = t & 31;   // rows tx + 32*i
        const int ty = t >> 5;   // k = ty*8 + kk
        ull acc[8][4];
        #pragma unroll
        for (int i = 0; i < 8; i++)
            #pragma unroll
            for (int p = 0; p < 4; p++) acc[i][p] = 0ull;

        #pragma unroll 4
        for (int j4 = 0; j4 < 16; ++j4) {
            float4 xv[8];
            #pragma unroll
            for (int i = 0; i < 8; i++)
                xv[i] = *(const float4*)&x_s[(tx + 32 * i) * XPAD + j4 * 4];
            #pragma unroll
            for (int jj = 0; jj < 4; ++jj) {
                ull cp[4];
                #pragma unroll
                for (int p = 0; p < 4; p++)
                    cp[p] = *(const ull*)&CT_s[(j4 * 4 + jj) * CTPAD + ty * 8 + 2 * p];
                #pragma unroll
                for (int i = 0; i < 8; i++) {
                    float xs = (jj == 0) ? xv[i].x : (jj == 1) ? xv[i].y
                             : (jj == 2) ? xv[i].z : xv[i].w;
                    ull xd = pack2(xs, xs);
                    #pragma unroll
                    for (int p = 0; p < 4; p++) acc[i][p] = ffma2(xd, cp[p], acc[i][p]);
                }
            }
        }
        // finish d2 and store to r_s[row][k]
        #pragma unroll
        for (int i = 0; i < 8; i++) {
            int row = tx + 32 * i;
            float x2v = x2_s[row];
            #pragma unroll
            for (int p = 0; p < 4; p++) {
                float da, db;
                unpack2(acc[i][p], da, db);
                int k0 = ty * 8 + 2 * p;
                float d2a = fmaxf(fmaf(-2.f, da, x2v + c2_s[k0]), 0.f);
                float d2b = fmaxf(fmaf(-2.f, db, x2v + c2_s[k0 + 1]), 0.f);
                *(float2*)&r_s[row * RPAD + k0] = make_float2(d2a, d2b);
            }
        }
    }
    __syncthreads();

    // ---- softmax per row (thread t owns row t)
    {
        float ev[64];
        const float4* rr = (const float4*)&r_s[t * RPAD];
        #pragma unroll
        for (int q = 0; q < 16; ++q) {
            float4 v = rr[q];
            ev[4 * q] = v.x; ev[4 * q + 1] = v.y; ev[4 * q + 2] = v.z; ev[4 * q + 3] = v.w;
        }
        float m = ev[0];
        #pragma unroll
        for (int k = 1; k < 64; ++k) m = fminf(m, ev[k]);
        float Z = 0.f, ln = 0.f;
        #pragma unroll
        for (int k = 0; k < 64; ++k) {
            float e = __expf(m - ev[k]);
            ln = fmaf(e, ev[k], ln);
            Z += e;
            ev[k] = e;
        }
        float invZ = 1.0f / Z;
        float4* rw = (float4*)&r_s[t * RPAD];
        #pragma unroll
        for (int q = 0; q < 16; ++q)
            rw[q] = make_float4(ev[4 * q] * invZ, ev[4 * q + 1] * invZ,
                                ev[4 * q + 2] * invZ, ev[4 * q + 3] * invZ);
        float lrow = ln * invZ;
        #pragma unroll
        for (int o = 16; o; o >>= 1) lrow += __shfl_xor_sync(0xffffffffu, lrow, o);
        if ((t & 31) == 0) red[t >> 5] = lrow;
    }
    __syncthreads();
    if (t == 0) {
        float s = 0.f;
        #pragma unroll
        for (int w = 0; w < 8; w++) s += red[w];
        atomicAdd(&g_loss, s);
    }
    __syncthreads();

    // ---- phase 2: Cacc += r^T x (4k x 4j per thread, f32x2 packed over j-pairs)
    {
        const int kg = t & 15;   // k = kg*4 + kk
        const int jg = t >> 4;   // j = jg*4 + jj
        ull accA[4], accB[4];
        float csum[4];
        #pragma unroll
        for (int kk = 0; kk < 4; kk++) { accA[kk] = 0ull; accB[kk] = 0ull; csum[kk] = 0.f; }

        #pragma unroll 4
        for (int row = 0; row < TILE; ++row) {
            float4 rv = *(const float4*)&r_s[row * RPAD + kg * 4];
            float4 xv = *(const float4*)&x_s[row * XPAD + jg * 4];
            ull xlo = pack2(xv.x, xv.y);
            ull xhi = pack2(xv.z, xv.w);
            float ra[4] = {rv.x, rv.y, rv.z, rv.w};
            #pragma unroll
            for (int kk = 0; kk < 4; kk++) {
                ull rd = pack2(ra[kk], ra[kk]);
                accA[kk] = ffma2(rd, xlo, accA[kk]);
                accB[kk] = ffma2(rd, xhi, accB[kk]);
            }
            if (jg == 0) {
                #pragma unroll
                for (int kk = 0; kk < 4; kk++) csum[kk] += ra[kk];
            }
        }
        #pragma unroll
        for (int kk = 0; kk < 4; kk++) {
            int k = kg * 4 + kk;
            int base = k * DLAT + jg * 4;
            float a0, a1, a2, a3;
            unpack2(accA[kk], a0, a1);
            unpack2(accB[kk], a2, a3);
            atomicAdd(&g_Cacc[base + 0], a0);
            atomicAdd(&g_Cacc[base + 1], a1);
            atomicAdd(&g_Cacc[base + 2], a2);
            atomicAdd(&g_Cacc[base + 3], a3);
        }
        if (jg == 0) {
            #pragma unroll
            for (int kk = 0; kk < 4; kk++) atomicAdd(&g_colsum[kg * 4 + kk], csum[kk]);
        }
    }
}

// ---------------------------------------------------------------------------
// normalize C, zero accumulators, snapshot loss
// ---------------------------------------------------------------------------
__global__ void norm_kernel() {
    int t = threadIdx.x;
    for (int i = t; i < KC * DLAT; i += 256) {
        float cs = g_colsum[i >> 6];
        g_C[i] = g_Cacc[i] / (cs + EPSV);
        g_Cacc[i] = 0.f;
    }
    __syncthreads();
    if (t < KC) g_colsum[t] = 0.f;
    if (t == 0) { g_loss_final = g_loss; g_loss = 0.f; }
}

__global__ void final_kernel(float* out) {
    out[0] = (float)(g_dloss * (1.0 / ((double)NROWS * (double)DDATA)))
           + ALPHA * (g_loss_final / (float)NROWS);
}

// ---------------------------------------------------------------------------
extern "C" void kernel_launch(void* const* d_in, const int* in_sizes, int n_in,
                              void* d_out, int out_size) {
    const float* X   = (const float*)d_in[0];
    const float* enc = (const float*)d_in[1];
    const float* dec = (const float*)d_in[2];
    float* out = (float*)d_out;

    size_t smem = (size_t)(TILE * XPAD + TILE * RPAD + DLAT * CTPAD + TILE + KC + 8)
                  * sizeof(float);
    cudaFuncSetAttribute(kmeans_iter, cudaFuncAttributeMaxDynamicSharedMemorySize,
                         (int)smem);

    init_kernel<<<16, 256>>>(enc);
    decoder_kernel<<<1184, 256>>>((const float4*)X, (const float4*)dec,
                                  (NROWS * DDATA) / 4);
    for (int it = 0; it < NITER; ++it) {
        kmeans_iter<<<NROWS / TILE, NT, smem>>>(enc);
        norm_kernel<<<1, 256>>>();
    }
    final_kernel<<<1, 1>>>(out);
}

// round 2
// speedup vs baseline: 1.1385x; 1.1385x over previous
#include <cuda_runtime.h>

#define NROWS 65536
#define DDATA 512
#define DLAT  64
#define KC    64
#define TILE  128
#define NT    256
#define NBLK  (NROWS / TILE)     // 512
#define NITER 10
#define EPSV  1e-8f
#define ALPHA 0.001f

#define XPAD  68
#define RPAD  68
#define CTPAD 66

typedef unsigned long long ull;

struct AccBuf { float acc[KC * DLAT]; float cs[KC]; };
__device__ AccBuf g_acc[2];
struct LossBuf { float loss; float pad; double dloss; };
__device__ LossBuf g_l;

__device__ __forceinline__ ull pack2(float a, float b) {
    ull r; asm("mov.b64 %0, {%1, %2};" : "=l"(r) : "f"(a), "f"(b)); return r;
}
__device__ __forceinline__ void unpack2(ull v, float& a, float& b) {
    asm("mov.b64 {%0, %1}, %2;" : "=f"(a), "=f"(b) : "l"(v));
}
__device__ __forceinline__ ull ffma2(ull a, ull b, ull c) {
    ull d; asm("fma.rn.f32x2 %0, %1, %2, %3;" : "=l"(d) : "l"(a), "l"(b), "l"(c)); return d;
}
__device__ __forceinline__ ull add2(ull a, ull b) {
    ull d; asm("add.rn.f32x2 %0, %1, %2;" : "=l"(d) : "l"(a), "l"(b)); return d;
}

// ---------------------------------------------------------------------------
// Fused k-means iteration (+ a slice of the decoder loss):
//  - build C in smem (from enc on iter0, else acc[rd]/(cs[rd]+eps))
//  - phase 1: d2 GEMM (f32x2), softmax -> r (and loss on last iter)
//  - phase 2: acc[wr] += r^T x, cs[wr] += colsum(r)   (skipped on last iter)
// ---------------------------------------------------------------------------
template<bool FROM_ENC, bool DO_LOSS, bool DO_P2>
__global__ __launch_bounds__(NT, 2) void kmeans_iter(
    const float* __restrict__ enc,
    const float4* __restrict__ X, const float4* __restrict__ Dc,
    int decB, int decE, int rd, int wr)
{
    extern __shared__ float sm[];
    float* x_s   = sm;                        // [TILE][XPAD]
    float* r_s   = x_s + TILE * XPAD;         // [TILE][RPAD]
    float* CT_s  = r_s + TILE * RPAD;         // [DLAT][CTPAD]  CT_s[j][k]
    float* x2_s  = CT_s + DLAT * CTPAD;       // [TILE]
    float* inv_s = x2_s + TILE;               // [KC]
    float* c2_s  = inv_s + KC;                // [KC]
    float* red_s = c2_s + KC;                 // [8]
    float* dec_s = red_s + 8;                 // [8]

    const int t = threadIdx.x;
    const int row0 = blockIdx.x * TILE;

    // ---- build C (transposed) in smem
    if (!FROM_ENC) {
        if (t < KC) inv_s[t] = 1.0f / (g_acc[rd].cs[t] + EPSV);
        __syncthreads();
        for (int i = t; i < KC * DLAT; i += NT) {
            int k = i >> 6, j = i & 63;
            CT_s[j * CTPAD + k] = g_acc[rd].acc[i] * inv_s[k];
        }
    } else {
        for (int i = t; i < KC * DLAT; i += NT) {
            int k = i >> 6, j = i & 63;
            CT_s[j * CTPAD + k] = enc[i];
        }
    }

    // ---- x tile
    for (int i = t; i < TILE * DLAT; i += NT) {
        int r = i >> 6, j = i & 63;
        x_s[r * XPAD + j] = enc[(row0 + r) * DLAT + j];
    }

    // ---- decoder loss slice (overlaps with smem fills / compute)
    {
        float ds = 0.f;
        for (int i = decB + blockIdx.x * NT + t; i < decE; i += NBLK * NT) {
            float4 a = X[i], b = Dc[i];
            float dx = a.x - b.x, dy = a.y - b.y, dz = a.z - b.z, dw = a.w - b.w;
            ds = fmaf(dx, dx, fmaf(dy, dy, fmaf(dz, dz, fmaf(dw, dw, ds))));
        }
        #pragma unroll
        for (int o = 16; o; o >>= 1) ds += __shfl_xor_sync(0xffffffffu, ds, o);
        if ((t & 31) == 0) dec_s[t >> 5] = ds;
    }
    __syncthreads();
    if (t == 0) {
        double s = 0.0;
        #pragma unroll
        for (int w = 0; w < 8; w++) s += (double)dec_s[w];
        atomicAdd(&g_l.dloss, s);
    }

    // ---- |x|^2 (threads 0..127) and |c|^2 (threads 128..191) in parallel
    if (t < TILE) {
        float s = 0.f;
        const float4* xr = (const float4*)&x_s[t * XPAD];
        #pragma unroll
        for (int q = 0; q < 16; ++q) {
            float4 v = xr[q];
            s = fmaf(v.x, v.x, fmaf(v.y, v.y, fmaf(v.z, v.z, fmaf(v.w, v.w, s))));
        }
        x2_s[t] = s;
    } else if (t < TILE + KC) {
        int k = t - TILE;
        float s = 0.f;
        #pragma unroll
        for (int j = 0; j < DLAT; ++j) {
            float v = CT_s[j * CTPAD + k];
            s = fmaf(v, v, s);
        }
        c2_s[k] = s;
    }
    __syncthreads();

    // ---- phase 1: 4-row x 8-k micro-tile, f32x2 over k-pairs
    {
        const int tx = t & 31;   // rows tx + 32*i (i<4)
        const int ty = t >> 5;   // k = ty*8 + ...
        ull acc[4][4];
        #pragma unroll
        for (int i = 0; i < 4; i++)
            #pragma unroll
            for (int p = 0; p < 4; p++) acc[i][p] = 0ull;

        #pragma unroll 4
        for (int j4 = 0; j4 < 16; ++j4) {
            float4 xv[4];
            #pragma unroll
            for (int i = 0; i < 4; i++)
                xv[i] = *(const float4*)&x_s[(tx + 32 * i) * XPAD + j4 * 4];
            #pragma unroll
            for (int jj = 0; jj < 4; ++jj) {
                ull cp[4];
                #pragma unroll
                for (int p = 0; p < 4; p++)
                    cp[p] = *(const ull*)&CT_s[(j4 * 4 + jj) * CTPAD + ty * 8 + 2 * p];
                #pragma unroll
                for (int i = 0; i < 4; i++) {
                    float xs = (jj == 0) ? xv[i].x : (jj == 1) ? xv[i].y
                             : (jj == 2) ? xv[i].z : xv[i].w;
                    ull xd = pack2(xs, xs);
                    #pragma unroll
                    for (int p = 0; p < 4; p++) acc[i][p] = ffma2(xd, cp[p], acc[i][p]);
                }
            }
        }
        #pragma unroll
        for (int i = 0; i < 4; i++) {
            int row = tx + 32 * i;
            float x2v = x2_s[row];
            #pragma unroll
            for (int p = 0; p < 4; p++) {
                float da, db;
                unpack2(acc[i][p], da, db);
                int k0 = ty * 8 + 2 * p;
                float d2a = fmaxf(fmaf(-2.f, da, x2v + c2_s[k0]), 0.f);
                float d2b = fmaxf(fmaf(-2.f, db, x2v + c2_s[k0 + 1]), 0.f);
                *(float2*)&r_s[row * RPAD + k0] = make_float2(d2a, d2b);
            }
        }
    }
    __syncthreads();

    // ---- softmax (threads 0..127, one row each)
    if (t < TILE) {
        float ev[64];
        const float4* rr = (const float4*)&r_s[t * RPAD];
        #pragma unroll
        for (int q = 0; q < 16; ++q) {
            float4 v = rr[q];
            ev[4 * q] = v.x; ev[4 * q + 1] = v.y; ev[4 * q + 2] = v.z; ev[4 * q + 3] = v.w;
        }
        float m = ev[0];
        #pragma unroll
        for (int k = 1; k < 64; ++k) m = fminf(m, ev[k]);
        float Z = 0.f, ln = 0.f;
        #pragma unroll
        for (int k = 0; k < 64; ++k) {
            float e = __expf(m - ev[k]);
            ln = fmaf(e, ev[k], ln);
            Z += e;
            ev[k] = e;
        }
        float invZ = 1.0f / Z;
        float4* rw = (float4*)&r_s[t * RPAD];
        #pragma unroll
        for (int q = 0; q < 16; ++q)
            rw[q] = make_float4(ev[4 * q] * invZ, ev[4 * q + 1] * invZ,
                                ev[4 * q + 2] * invZ, ev[4 * q + 3] * invZ);
        if (DO_LOSS) {
            float lrow = ln * invZ;
            #pragma unroll
            for (int o = 16; o; o >>= 1) lrow += __shfl_xor_sync(0xffffffffu, lrow, o);
            if ((t & 31) == 0) red_s[t >> 5] = lrow;
        }
    }
    __syncthreads();
    if (DO_LOSS && t == 0) {
        float s = 0.f;
        #pragma unroll
        for (int w = 0; w < 4; w++) s += red_s[w];
        atomicAdd(&g_l.loss, s);
    }

    if (!DO_P2) return;

    // ---- phase 2: acc[wr] += r^T x  (f32x2 over k-pairs, packed r from smem)
    {
        const int jg  = t & 15;          // j block: j0 = 4*jg
        const int kh  = t >> 4;          // 0..15
        const int kpg = kh & 7;          // k block: k0 = 8*kpg (4 ull pairs)
        const int half = kh >> 3;        // row half
        const int j0 = jg * 4, k0 = kpg * 8;
        const int rb = half * (TILE / 2), re = rb + (TILE / 2);

        ull a2[4][4];                    // [j][kpair]
        ull csum[4];
        #pragma unroll
        for (int j = 0; j < 4; j++)
            #pragma unroll
            for (int p = 0; p < 4; p++) a2[j][p] = 0ull;
        #pragma unroll
        for (int p = 0; p < 4; p++) csum[p] = 0ull;

        #pragma unroll 4
        for (int row = rb; row < re; ++row) {
            ulonglong2 rv01 = *(const ulonglong2*)&r_s[row * RPAD + k0];
            ulonglong2 rv23 = *(const ulonglong2*)&r_s[row * RPAD + k0 + 4];
            ull rv[4] = { rv01.x, rv01.y, rv23.x, rv23.y };
            float4 xv = *(const float4*)&x_s[row * XPAD + j0];
            ull xd[4] = { pack2(xv.x, xv.x), pack2(xv.y, xv.y),
                          pack2(xv.z, xv.z), pack2(xv.w, xv.w) };
            #pragma unroll
            for (int j = 0; j < 4; j++)
                #pragma unroll
                for (int p = 0; p < 4; p++) a2[j][p] = ffma2(xd[j], rv[p], a2[j][p]);
            if (jg == 0) {
                #pragma unroll
                for (int p = 0; p < 4; p++) csum[p] = add2(csum[p], rv[p]);
            }
        }

        // combine the two row-halves via smem (reuse r_s)
        __syncthreads();
        ull* cb = (ull*)r_s;
        const int pos = kpg * 16 + jg;   // 0..127
        if (half == 1) {
            #pragma unroll
            for (int j = 0; j < 4; j++)
                #pragma unroll
                for (int p = 0; p < 4; p++) cb[pos * 16 + j * 4 + p] = a2[j][p];
            if (jg == 0) {
                #pragma unroll
                for (int p = 0; p < 4; p++) cb[2048 + kpg * 4 + p] = csum[p];
            }
        }
        __syncthreads();
        if (half == 0) {
            #pragma unroll
            for (int j = 0; j < 4; j++)
                #pragma unroll
                for (int p = 0; p < 4; p++)
                    a2[j][p] = add2(a2[j][p], cb[pos * 16 + j * 4 + p]);
            #pragma unroll
            for (int kk = 0; kk < 8; kk++) {
                int k = k0 + kk, p = kk >> 1;
                float* base = &g_acc[wr].acc[k * DLAT + j0];
                #pragma unroll
                for (int j = 0; j < 4; j++) {
                    float lo, hi;
                    unpack2(a2[j][p], lo, hi);
                    atomicAdd(&base[j], (kk & 1) ? hi : lo);
                }
            }
            if (jg == 0) {
                #pragma unroll
                for (int p = 0; p < 4; p++) {
                    float lo, hi;
                    unpack2(add2(csum[p], cb[2048 + kpg * 4 + p]), lo, hi);
                    atomicAdd(&g_acc[wr].cs[k0 + 2 * p], lo);
                    atomicAdd(&g_acc[wr].cs[k0 + 2 * p + 1], hi);
                }
            }
        }
    }
}

__global__ void final_kernel(float* out) {
    out[0] = (float)(g_l.dloss * (1.0 / ((double)NROWS * (double)DDATA)))
           + ALPHA * (g_l.loss / (float)NROWS);
}

// ---------------------------------------------------------------------------
extern "C" void kernel_launch(void* const* d_in, const int* in_sizes, int n_in,
                              void* d_out, int out_size) {
    const float*  X   = (const float*)d_in[0];
    const float*  enc = (const float*)d_in[1];
    const float*  dec = (const float*)d_in[2];
    float* out = (float*)d_out;
    const float4* X4 = (const float4*)X;
    const float4* D4 = (const float4*)dec;

    const size_t smem = (size_t)(TILE * XPAD + TILE * RPAD + DLAT * CTPAD
                                 + TILE + KC + KC + 8 + 8) * sizeof(float);
    cudaFuncSetAttribute(kmeans_iter<true,  false, true >,
                         cudaFuncAttributeMaxDynamicSharedMemorySize, (int)smem);
    cudaFuncSetAttribute(kmeans_iter<false, false, true >,
                         cudaFuncAttributeMaxDynamicSharedMemorySize, (int)smem);
    cudaFuncSetAttribute(kmeans_iter<false, true,  false>,
                         cudaFuncAttributeMaxDynamicSharedMemorySize, (int)smem);

    void *accAddr, *lAddr;
    cudaGetSymbolAddress(&accAddr, g_acc);
    cudaGetSymbolAddress(&lAddr, g_l);

    const int N4 = NROWS * DDATA / 4;
    auto chunkB = [&](int it) { return (int)((long long)it * N4 / NITER); };

    cudaMemsetAsync(lAddr, 0, sizeof(LossBuf));

    // iter 0: C from enc
    cudaMemsetAsync((char*)accAddr + 0 * sizeof(AccBuf), 0, sizeof(AccBuf));
    kmeans_iter<true, false, true><<<NBLK, NT, smem>>>(
        enc, X4, D4, chunkB(0), chunkB(1), 0, 0);

    // iters 1..8
    for (int it = 1; it <= 8; ++it) {
        int wr = it & 1, rdb = wr ^ 1;
        cudaMemsetAsync((char*)accAddr + (size_t)wr * sizeof(AccBuf), 0, sizeof(AccBuf));
        kmeans_iter<false, false, true><<<NBLK, NT, smem>>>(
            enc, X4, D4, chunkB(it), chunkB(it + 1), rdb, wr);
    }

    // iter 9: loss only, no C update
    kmeans_iter<false, true, false><<<NBLK, NT, smem>>>(
        enc, X4, D4, chunkB(9), chunkB(10), 0, 0);

    final_kernel<<<1, 1>>>(out);
}

// round 3
// speedup vs baseline: 1.3490x; 1.1849x over previous
#include <cuda_runtime.h>

#define NROWS 65536
#define DDATA 512
#define DLAT  64
#define KC    64
#define TILE  64
#define NT    256
#define NBLK  (NROWS / TILE)     // 1024
#define NITER 10
#define EPSV  1e-8f
#define ALPHA 0.001f

#define XP 68
#define RP 68
#define CP 68

typedef unsigned long long ull;

struct AccBuf { float acc[KC * DLAT]; float cs[KC]; };
__device__ AccBuf g_acc[3];
struct LossBuf { float loss; float pad; double dloss; };
__device__ LossBuf g_l;

__device__ __forceinline__ ull pack2(float a, float b) {
    ull r; asm("mov.b64 %0, {%1, %2};" : "=l"(r) : "f"(a), "f"(b)); return r;
}
__device__ __forceinline__ void unpack2(ull v, float& a, float& b) {
    asm("mov.b64 {%0, %1}, %2;" : "=f"(a), "=f"(b) : "l"(v));
}
__device__ __forceinline__ ull ffma2(ull a, ull b, ull c) {
    ull d; asm("fma.rn.f32x2 %0, %1, %2, %3;" : "=l"(d) : "l"(a), "l"(b), "l"(c)); return d;
}
__device__ __forceinline__ ull add2(ull a, ull b) {
    ull d; asm("add.rn.f32x2 %0, %1, %2;" : "=l"(d) : "l"(a), "l"(b)); return d;
}
__device__ __forceinline__ void red4(float* p, float a, float b, float c, float d) {
    asm volatile("red.global.add.v4.f32 [%0], {%1,%2,%3,%4};"
                 :: "l"(p), "f"(a), "f"(b), "f"(c), "f"(d) : "memory");
}

__global__ void init_kernel() {
    int gid = blockIdx.x * 256 + threadIdx.x;
    if (gid < KC * DLAT) g_acc[0].acc[gid] = 0.f;
    if (gid < KC) g_acc[0].cs[gid] = 0.f;
    if (gid == 0) { g_l.loss = 0.f; g_l.dloss = 0.0; }
}

// ---------------------------------------------------------------------------
// Fused k-means iteration + decoder-loss slice.
//  CT_s[j][k] = C[k][j]; phase1 d2 GEMM (f32x2 over k) -> softmax -> r;
//  phase2 acc[wr] += r^T x via red.v4; zeroes acc[zr] for iteration it+1.
// ---------------------------------------------------------------------------
template<bool FROM_ENC, bool DO_LOSS, bool DO_P2>
__global__ __launch_bounds__(NT, 4) void kmeans_iter(
    const float* __restrict__ enc,
    const float4* __restrict__ X, const float4* __restrict__ Dc,
    int decB, int decE, int rd, int wr, int zr)
{
    extern __shared__ float sm[];
    float* x_s   = sm;                   // [TILE][XP]
    float* r_s   = x_s + TILE * XP;      // [TILE][RP]  d2 then r
    float* CT_s  = r_s + TILE * RP;      // [DLAT][CP]
    float* x2_s  = CT_s + DLAT * CP;     // [TILE]
    float* c2_s  = x2_s + TILE;          // [KC]
    float* red_s = c2_s + KC;            // [8]
    float* dec_s = red_s + 8;            // [8]

    const int t = threadIdx.x;
    const int b = blockIdx.x;
    const int row0 = b * TILE;

    // ---- zero the accumulator buffer for iteration it+1 (3-buffer rotation)
    if (DO_P2) {
        int gid = b * NT + t;
        if (gid < KC * DLAT) g_acc[zr].acc[gid] = 0.f;
        if (gid < KC) g_acc[zr].cs[gid] = 0.f;
    }

    // ---- x tile (coalesced)
    for (int i = t; i < TILE * DLAT; i += NT) {
        int r = i >> 6, j = i & 63;
        x_s[r * XP + j] = enc[(row0 + r) * DLAT + j];
    }
    // ---- CT build (transposed store; 4-way conflict is negligible one-time cost)
    if (FROM_ENC) {
        for (int i = t; i < KC * DLAT; i += NT) {
            int k = i >> 6, j = i & 63;
            CT_s[j * CP + k] = enc[i];
        }
    } else {
        for (int i = t; i < KC * DLAT; i += NT) {
            int k = i >> 6, j = i & 63;
            CT_s[j * CP + k] = g_acc[rd].acc[i] * (1.0f / (g_acc[rd].cs[k] + EPSV));
        }
    }

    // ---- decoder loss slice (global loads overlap smem fills)
    {
        float ds0 = 0.f, ds1 = 0.f;
        const int stride = NBLK * NT;
        int i = decB + b * NT + t;
        for (; i + stride < decE; i += 2 * stride) {
            float4 a0 = X[i], b0 = Dc[i];
            float4 a1 = X[i + stride], b1 = Dc[i + stride];
            float d0 = a0.x - b0.x, d1 = a0.y - b0.y, d2 = a0.z - b0.z, d3 = a0.w - b0.w;
            ds0 = fmaf(d0, d0, fmaf(d1, d1, fmaf(d2, d2, fmaf(d3, d3, ds0))));
            float e0 = a1.x - b1.x, e1 = a1.y - b1.y, e2 = a1.z - b1.z, e3 = a1.w - b1.w;
            ds1 = fmaf(e0, e0, fmaf(e1, e1, fmaf(e2, e2, fmaf(e3, e3, ds1))));
        }
        if (i < decE) {
            float4 a0 = X[i], b0 = Dc[i];
            float d0 = a0.x - b0.x, d1 = a0.y - b0.y, d2 = a0.z - b0.z, d3 = a0.w - b0.w;
            ds0 = fmaf(d0, d0, fmaf(d1, d1, fmaf(d2, d2, fmaf(d3, d3, ds0))));
        }
        float ds = ds0 + ds1;
        #pragma unroll
        for (int o = 16; o; o >>= 1) ds += __shfl_xor_sync(0xffffffffu, ds, o);
        if ((t & 31) == 0) dec_s[t >> 5] = ds;
    }
    __syncthreads();

    // ---- |x|^2 (t<64), |c|^2 (64<=t<128), decoder atomic (t==255)
    if (t < TILE) {
        float s = 0.f;
        const float4* xr = (const float4*)&x_s[t * XP];
        #pragma unroll
        for (int q = 0; q < 16; ++q) {
            float4 v = xr[q];
            s = fmaf(v.x, v.x, fmaf(v.y, v.y, fmaf(v.z, v.z, fmaf(v.w, v.w, s))));
        }
        x2_s[t] = s;
    } else if (t < TILE + KC) {
        int k = t - TILE;
        float s = 0.f;
        #pragma unroll
        for (int j = 0; j < DLAT; ++j) {
            float v = CT_s[j * CP + k];
            s = fmaf(v, v, s);
        }
        c2_s[k] = s;
    } else if (t == NT - 1) {
        double s = 0.0;
        #pragma unroll
        for (int w = 0; w < 8; w++) s += (double)dec_s[w];
        atomicAdd(&g_l.dloss, s);
    }
    __syncthreads();

    // ---- phase 1: thread = 2 rows x 8 k, f32x2 over k-pairs, c warp-broadcast
    {
        const int tx = t & 31;        // rows tx, tx+32
        const int ty = t >> 5;        // k0 = ty*8
        const int k0 = ty * 8;
        ull a0[4], a1[4];
        #pragma unroll
        for (int p = 0; p < 4; p++) { a0[p] = 0ull; a1[p] = 0ull; }
        const float* xr0 = &x_s[tx * XP];
        const float* xr1 = &x_s[(tx + 32) * XP];

        #pragma unroll 4
        for (int j4 = 0; j4 < 16; ++j4) {
            float4 xa = *(const float4*)&xr0[j4 * 4];
            float4 xb = *(const float4*)&xr1[j4 * 4];
            #pragma unroll
            for (int jj = 0; jj < 4; ++jj) {
                const float* crow = &CT_s[(j4 * 4 + jj) * CP + k0];
                ulonglong2 cpq = *(const ulonglong2*)crow;
                ulonglong2 crs = *(const ulonglong2*)(crow + 4);
                float s0 = (jj == 0) ? xa.x : (jj == 1) ? xa.y : (jj == 2) ? xa.z : xa.w;
                float s1 = (jj == 0) ? xb.x : (jj == 1) ? xb.y : (jj == 2) ? xb.z : xb.w;
                ull xd0 = pack2(s0, s0), xd1 = pack2(s1, s1);
                a0[0] = ffma2(xd0, cpq.x, a0[0]); a0[1] = ffma2(xd0, cpq.y, a0[1]);
                a0[2] = ffma2(xd0, crs.x, a0[2]); a0[3] = ffma2(xd0, crs.y, a0[3]);
                a1[0] = ffma2(xd1, cpq.x, a1[0]); a1[1] = ffma2(xd1, cpq.y, a1[1]);
                a1[2] = ffma2(xd1, crs.x, a1[2]); a1[3] = ffma2(xd1, crs.y, a1[3]);
            }
        }
        float x20 = x2_s[tx], x21 = x2_s[tx + 32];
        #pragma unroll
        for (int p = 0; p < 4; p++) {
            float c2a = c2_s[k0 + 2 * p], c2b = c2_s[k0 + 2 * p + 1];
            float da, db;
            unpack2(a0[p], da, db);
            *(float2*)&r_s[tx * RP + k0 + 2 * p] =
                make_float2(fmaxf(fmaf(-2.f, da, x20 + c2a), 0.f),
                            fmaxf(fmaf(-2.f, db, x20 + c2b), 0.f));
            unpack2(a1[p], da, db);
            *(float2*)&r_s[(tx + 32) * RP + k0 + 2 * p] =
                make_float2(fmaxf(fmaf(-2.f, da, x21 + c2a), 0.f),
                            fmaxf(fmaf(-2.f, db, x21 + c2b), 0.f));
        }
    }
    __syncthreads();

    // ---- softmax: thread = (row = t>>2, k-quarter = t&3), quad combine via shfl
    {
        const int row = t >> 2, q = t & 3;
        float* rp = &r_s[row * RP + q * 16];
        float d2v[16];
        #pragma unroll
        for (int v4i = 0; v4i < 4; ++v4i) {
            float4 v = *(const float4*)&rp[v4i * 4];
            d2v[4 * v4i] = v.x; d2v[4 * v4i + 1] = v.y;
            d2v[4 * v4i + 2] = v.z; d2v[4 * v4i + 3] = v.w;
        }
        float m = d2v[0];
        #pragma unroll
        for (int k = 1; k < 16; ++k) m = fminf(m, d2v[k]);
        m = fminf(m, __shfl_xor_sync(0xffffffffu, m, 1));
        m = fminf(m, __shfl_xor_sync(0xffffffffu, m, 2));
        float Z = 0.f, ln = 0.f;
        #pragma unroll
        for (int k = 0; k < 16; ++k) {
            float e = __expf(m - d2v[k]);
            if (DO_LOSS) ln = fmaf(e, d2v[k], ln);
            Z += e;
            d2v[k] = e;
        }
        Z += __shfl_xor_sync(0xffffffffu, Z, 1);
        Z += __shfl_xor_sync(0xffffffffu, Z, 2);
        float invZ = 1.0f / Z;
        if (DO_P2) {
            #pragma unroll
            for (int v4i = 0; v4i < 4; ++v4i)
                *(float4*)&rp[v4i * 4] =
                    make_float4(d2v[4 * v4i] * invZ, d2v[4 * v4i + 1] * invZ,
                                d2v[4 * v4i + 2] * invZ, d2v[4 * v4i + 3] * invZ);
        }
        if (DO_LOSS) {
            ln += __shfl_xor_sync(0xffffffffu, ln, 1);
            ln += __shfl_xor_sync(0xffffffffu, ln, 2);
            float lrow = ln * invZ * 0.25f;   // 4 lanes share each row
            #pragma unroll
            for (int o = 16; o; o >>= 1) lrow += __shfl_xor_sync(0xffffffffu, lrow, o);
            if ((t & 31) == 0) red_s[t >> 5] = lrow;
        }
    }
    __syncthreads();
    if (DO_LOSS && t == 0) {
        float s = 0.f;
        #pragma unroll
        for (int w = 0; w < 8; w++) s += red_s[w];
        atomicAdd(&g_l.loss, s);
    }
    if (!DO_P2) return;

    // ---- phase 2: thread = 4j x 4k; r warp-broadcast, f32x2 over k-pairs
    {
        const int jg = t & 15, kq = t >> 4;
        const int j0 = jg * 4, k0 = kq * 4;
        ull a00 = 0, a01 = 0, a10 = 0, a11 = 0, a20 = 0, a21 = 0, a30 = 0, a31 = 0;
        ull cs0 = 0, cs1 = 0;

        #pragma unroll 4
        for (int row = 0; row < TILE; ++row) {
            ulonglong2 rv = *(const ulonglong2*)&r_s[row * RP + k0];
            float4 xv = *(const float4*)&x_s[row * XP + j0];
            ull xd0 = pack2(xv.x, xv.x), xd1 = pack2(xv.y, xv.y);
            ull xd2 = pack2(xv.z, xv.z), xd3 = pack2(xv.w, xv.w);
            a00 = ffma2(xd0, rv.x, a00); a01 = ffma2(xd0, rv.y, a01);
            a10 = ffma2(xd1, rv.x, a10); a11 = ffma2(xd1, rv.y, a11);
            a20 = ffma2(xd2, rv.x, a20); a21 = ffma2(xd2, rv.y, a21);
            a30 = ffma2(xd3, rv.x, a30); a31 = ffma2(xd3, rv.y, a31);
            if (jg == 0) { cs0 = add2(cs0, rv.x); cs1 = add2(cs1, rv.y); }
        }
        float w0[4], w1[4], w2[4], w3[4];
        unpack2(a00, w0[0], w0[1]); unpack2(a01, w0[2], w0[3]);
        unpack2(a10, w1[0], w1[1]); unpack2(a11, w1[2], w1[3]);
        unpack2(a20, w2[0], w2[1]); unpack2(a21, w2[2], w2[3]);
        unpack2(a30, w3[0], w3[1]); unpack2(a31, w3[2], w3[3]);
        #pragma unroll
        for (int kk = 0; kk < 4; ++kk)
            red4(&g_acc[wr].acc[(k0 + kk) * DLAT + j0], w0[kk], w1[kk], w2[kk], w3[kk]);
        if (jg == 0) {
            float c0, c1, c2, c3;
            unpack2(cs0, c0, c1); unpack2(cs1, c2, c3);
            red4(&g_acc[wr].cs[k0], c0, c1, c2, c3);
        }
    }
}

__global__ void final_kernel(float* out) {
    out[0] = (float)(g_l.dloss * (1.0 / ((double)NROWS * (double)DDATA)))
           + ALPHA * (g_l.loss / (float)NROWS);
}

// ---------------------------------------------------------------------------
extern "C" void kernel_launch(void* const* d_in, const int* in_sizes, int n_in,
                              void* d_out, int out_size) {
    const float* X   = (const float*)d_in[0];
    const float* enc = (const float*)d_in[1];
    const float* dec = (const float*)d_in[2];
    float* out = (float*)d_out;
    const float4* X4 = (const float4*)X;
    const float4* D4 = (const float4*)dec;

    const size_t smem = (size_t)(TILE * XP + TILE * RP + DLAT * CP
                                 + TILE + KC + 8 + 8) * sizeof(float);
    cudaFuncSetAttribute(kmeans_iter<true,  false, true >,
                         cudaFuncAttributeMaxDynamicSharedMemorySize, (int)smem);
    cudaFuncSetAttribute(kmeans_iter<false, false, true >,
                         cudaFuncAttributeMaxDynamicSharedMemorySize, (int)smem);
    cudaFuncSetAttribute(kmeans_iter<false, true,  false>,
                         cudaFuncAttributeMaxDynamicSharedMemorySize, (int)smem);

    const int N4 = NROWS * DDATA / 4;
    auto chunkB = [&](int it) { return (int)((long long)it * N4 / NITER); };

    init_kernel<<<17, 256>>>();

    // iter 0: C from enc; writes buf0 (pre-zeroed by init), zeroes buf1
    kmeans_iter<true, false, true><<<NBLK, NT, smem>>>(
        enc, X4, D4, chunkB(0), chunkB(1), 0, 0, 1);

    // iters 1..8: rd=(it-1)%3, wr=it%3 (zeroed last iter), zero (it+1)%3
    for (int it = 1; it <= 8; ++it) {
        kmeans_iter<false, false, true><<<NBLK, NT, smem>>>(
            enc, X4, D4, chunkB(it), chunkB(it + 1),
            (it - 1) % 3, it % 3, (it + 1) % 3);
    }

    // iter 9: loss only
    kmeans_iter<false, true, false><<<NBLK, NT, smem>>>(
        enc, X4, D4, chunkB(9), chunkB(10), 2, 0, 0);

    final_kernel<<<1, 1>>>(out);
}